// round 8
// baseline (speedup 1.0000x reference)
#include <cuda_runtime.h>
#include <cstddef>

// FCOS-style target assignment, one thread per output grid cell.
// out layout per scale: [B, S(j), S(i), 25] with channels
//   [0..19]  one-hot class map (OR over boxes covering cell)
//   [20..24] L/stride, T/stride, R/stride, B/stride, centerness
template<int S>
__global__ void assign_kernel(const float* __restrict__ bboxes,
                              const int*   __restrict__ labels,
                              float*       __restrict__ out)
{
    __shared__ float4 sbox[32];
    __shared__ int    slab[32];

    const int b = blockIdx.y;
    if (threadIdx.x < 32) {
        sbox[threadIdx.x] = reinterpret_cast<const float4*>(bboxes)[b * 32 + threadIdx.x];
        slab[threadIdx.x] = labels[b * 32 + threadIdx.x];
    }
    __syncthreads();

    const int cell = blockIdx.x * blockDim.x + threadIdx.x;
    if (cell >= S * S) return;
    const int ii = cell % S;   // x index (dim from cx)
    const int jj = cell / S;   // y index (dim from cy)

    const float stride = 416.0f / (float)S;
    const float inv_stride = (float)S / 416.0f;     // stride is 32/16/8 -> exact
    const float fii = (float)ii;
    const float fjj = (float)jj;
    const float cxc = (fii + 0.5f) * stride;        // pixel center along x
    const float cyc = (fjj + 0.5f) * stride;        // pixel center along y

    unsigned clsmask = 0u;
    float reg0 = 0.f, reg1 = 0.f, reg2 = 0.f, reg3 = 0.f, reg4 = 0.f;

    #pragma unroll 4
    for (int n = 0; n < 32; ++n) {
        const float4 bx = sbox[n];
        const float cx = bx.x, cy = bx.y, bw = bx.z, bh = bx.w;

        const float pos0 = floorf(cx * inv_stride);
        const float pos1 = floorf(cy * inv_stride);
        const float bp0  = floorf(0.5f * bw * inv_stride);
        const float bp1  = floorf(0.5f * bh * inv_stride);

        const bool ri = (fii >= pos0 - bp0) && (fii < pos0 + bp0);
        const bool rj = (fjj >= pos1 - bp1) && (fjj < pos1 + bp1);
        const bool region = ri && rj;

        if (region) clsmask |= (1u << slab[n]);

        const float hw = floorf(bw * 0.5f);
        const float hh = floorf(bh * 0.5f);
        const float l  = cxc - (cx - hw);
        const float r  = (cx + hw) - cxc;
        const float t  = cyc - (cy - hh);
        const float bo = (cy + hh) - cyc;

        const float mlr = fmaxf(l, r);
        const float mtb = fmaxf(t, bo);
        const float m   = fmaxf(mlr, mtb);

        bool band;
        if (S == 13)      band = (m > 256.0f);
        else if (S == 26) band = (m > 64.0f) && (m <= 256.0f);
        else              band = (m <= 64.0f);

        if (region && band) {
            const float regmax = fmaxf(fmaxf(fmaxf(reg0, reg1), fmaxf(reg2, reg3)), reg4);
            if (regmax == 0.0f || m < regmax) {
                const float cent = sqrtf(fminf(l, r) * fminf(t, bo) / (mlr * mtb));
                reg0 = fmaxf(l  * inv_stride, 0.0f);
                reg1 = fmaxf(t  * inv_stride, 0.0f);
                reg2 = fmaxf(r  * inv_stride, 0.0f);
                reg3 = fmaxf(bo * inv_stride, 0.0f);
                reg4 = fmaxf(cent, 0.0f);
            }
        }
    }

    float* o = out + ((size_t)(b * S + jj) * S + ii) * 25;
    #pragma unroll
    for (int c = 0; c < 20; ++c)
        o[c] = ((clsmask >> c) & 1u) ? 1.0f : 0.0f;
    o[20] = reg0; o[21] = reg1; o[22] = reg2; o[23] = reg3; o[24] = reg4;
}

extern "C" void kernel_launch(void* const* d_in, const int* in_sizes, int n_in,
                              void* d_out, int out_size)
{
    const float* image  = (const float*)d_in[0];
    const float* bboxes = (const float*)d_in[1];
    const int*   labels = (const int*)  d_in[2];
    float* out = (float*)d_out;

    const size_t n_img = (size_t)in_sizes[0];            // 64*3*416*416
    constexpr int B = 64;
    constexpr size_t T13 = (size_t)B * 13 * 13 * 25;
    constexpr size_t T26 = (size_t)B * 26 * 26 * 25;

    // Image passthrough: bulk D2D copy (graph-capturable).
    cudaMemcpyAsync(out, image, n_img * sizeof(float), cudaMemcpyDeviceToDevice);

    float* o13 = out + n_img;
    float* o26 = o13 + T13;
    float* o52 = o26 + T26;

    assign_kernel<13><<<dim3(1,  B), 256>>>(bboxes, labels, o13);
    assign_kernel<26><<<dim3(3,  B), 256>>>(bboxes, labels, o26);
    assign_kernel<52><<<dim3(11, B), 256>>>(bboxes, labels, o52);
}

// round 9
// speedup vs baseline: 1.3929x; 1.3929x over previous
#include <cuda_runtime.h>
#include <cstddef>

// ---- constants ----------------------------------------------------------
constexpr int BATCH = 64;
constexpr int C13 = BATCH * 13 * 13;            // 10816  (mult of 32)
constexpr int C26 = BATCH * 26 * 26;            // 43264  (mult of 32)
constexpr int C52 = BATCH * 52 * 52;            // 173056 (mult of 32)
constexpr int TOT_CELLS = C13 + C26 + C52;      // 227136
constexpr int THREADS = 256;
constexpr int ABLK = (TOT_CELLS + THREADS - 1) / THREADS;   // 888
constexpr int CBLK = 2368;                                   // copy-only blocks
constexpr int NB   = ABLK + CBLK;                            // 3256

// One FCOS cell: compute 25 output channels and store.
template<int S>
__device__ __forceinline__ void assign_cell(int local,
                                            const float4* __restrict__ bboxes4,
                                            const int*    __restrict__ labels,
                                            float*        __restrict__ out)
{
    const int b    = local / (S * S);
    const int cell = local % (S * S);
    const int ii = cell % S;   // x
    const int jj = cell / S;   // y

    const float stride     = 416.0f / (float)S;
    const float inv_stride = (float)S / 416.0f;   // exact (stride = 32/16/8)
    const float fii = (float)ii;
    const float fjj = (float)jj;
    const float cxc = (fii + 0.5f) * stride;
    const float cyc = (fjj + 0.5f) * stride;

    unsigned clsmask = 0u;
    float reg0 = 0.f, reg1 = 0.f, reg2 = 0.f, reg3 = 0.f, reg4 = 0.f;

    const float4* bb = bboxes4 + b * 32;
    const int*    lb = labels  + b * 32;

    #pragma unroll 4
    for (int n = 0; n < 32; ++n) {
        const float4 bx = __ldg(bb + n);
        const float cx = bx.x, cy = bx.y, bw = bx.z, bh = bx.w;

        const float pos0 = floorf(cx * inv_stride);
        const float pos1 = floorf(cy * inv_stride);
        const float bp0  = floorf(0.5f * bw * inv_stride);
        const float bp1  = floorf(0.5f * bh * inv_stride);

        const bool region = (fii >= pos0 - bp0) && (fii < pos0 + bp0) &&
                            (fjj >= pos1 - bp1) && (fjj < pos1 + bp1);

        if (region) clsmask |= (1u << __ldg(lb + n));

        const float hw = floorf(bw * 0.5f);
        const float hh = floorf(bh * 0.5f);
        const float l  = cxc - (cx - hw);
        const float r  = (cx + hw) - cxc;
        const float t  = cyc - (cy - hh);
        const float bo = (cy + hh) - cyc;

        const float mlr = fmaxf(l, r);
        const float mtb = fmaxf(t, bo);
        const float m   = fmaxf(mlr, mtb);

        bool band;
        if (S == 13)      band = (m > 256.0f);
        else if (S == 26) band = (m > 64.0f) && (m <= 256.0f);
        else              band = (m <= 64.0f);

        if (region && band) {
            const float regmax = fmaxf(fmaxf(fmaxf(reg0, reg1), fmaxf(reg2, reg3)), reg4);
            if (regmax == 0.0f || m < regmax) {
                const float cent = sqrtf(fminf(l, r) * fminf(t, bo) / (mlr * mtb));
                reg0 = fmaxf(l  * inv_stride, 0.0f);
                reg1 = fmaxf(t  * inv_stride, 0.0f);
                reg2 = fmaxf(r  * inv_stride, 0.0f);
                reg3 = fmaxf(bo * inv_stride, 0.0f);
                reg4 = fmaxf(cent, 0.0f);
            }
        }
    }

    float* o = out + (size_t)local * 25;   // [B, S(j), S(i), 25] is exactly local-major
    #pragma unroll
    for (int c = 0; c < 20; ++c)
        o[c] = ((clsmask >> c) & 1u) ? 1.0f : 0.0f;
    o[20] = reg0; o[21] = reg1; o[22] = reg2; o[23] = reg3; o[24] = reg4;
}

__global__ __launch_bounds__(THREADS)
void fused_kernel(const float4* __restrict__ img4,
                  float4*       __restrict__ out4,
                  int n4,
                  const float4* __restrict__ bboxes4,
                  const int*    __restrict__ labels,
                  float*        __restrict__ o13,
                  float*        __restrict__ o26,
                  float*        __restrict__ o52)
{
    // Phase 1: target assignment on the first ABLK blocks (warp-uniform scale:
    // C13 and C13+C26 are multiples of 32, so no intra-warp scale divergence).
    const int bid = blockIdx.x;
    if (bid < ABLK) {
        const int g = bid * THREADS + threadIdx.x;
        if (g < C13)              assign_cell<13>(g,             bboxes4, labels, o13);
        else if (g < C13 + C26)   assign_cell<26>(g - C13,       bboxes4, labels, o26);
        else if (g < TOT_CELLS)   assign_cell<52>(g - C13 - C26, bboxes4, labels, o52);
    }

    // Phase 2: all blocks copy the image, grid-stride over float4.
    const int stride = NB * THREADS;
    int i = bid * THREADS + threadIdx.x;
    // unrolled-by-2 main loop for a little more MLP
    for (; i + stride < n4; i += 2 * stride) {
        float4 a = img4[i];
        float4 b = img4[i + stride];
        out4[i]          = a;
        out4[i + stride] = b;
    }
    if (i < n4) out4[i] = img4[i];
}

extern "C" void kernel_launch(void* const* d_in, const int* in_sizes, int n_in,
                              void* d_out, int out_size)
{
    const float* image  = (const float*)d_in[0];
    const float* bboxes = (const float*)d_in[1];
    const int*   labels = (const int*)  d_in[2];
    float* out = (float*)d_out;

    const size_t n_img = (size_t)in_sizes[0];   // 33,226,752 (divisible by 4)
    const int n4 = (int)(n_img / 4);

    float* o13 = out + n_img;
    float* o26 = o13 + (size_t)BATCH * 13 * 13 * 25;
    float* o52 = o26 + (size_t)BATCH * 26 * 26 * 25;

    fused_kernel<<<NB, THREADS>>>((const float4*)image, (float4*)out, n4,
                                  (const float4*)bboxes, labels, o13, o26, o52);
}

// round 10
// speedup vs baseline: 1.4040x; 1.0080x over previous
#include <cuda_runtime.h>
#include <cstddef>

// ---- constants ----------------------------------------------------------
constexpr int BATCH = 64;
constexpr int C13 = BATCH * 13 * 13;            // 10816  (mult of 32)
constexpr int C26 = BATCH * 26 * 26;            // 43264  (mult of 32)
constexpr int C52 = BATCH * 52 * 52;            // 173056 (mult of 32)
constexpr int TOT_CELLS = C13 + C26 + C52;      // 227136
constexpr int THREADS = 256;
constexpr int ABLK = (TOT_CELLS + THREADS - 1) / THREADS;   // 888
constexpr int CBLK = 2368;                                   // copy-only blocks
constexpr int NB   = ABLK + CBLK;                            // 3256

// One FCOS cell: compute 25 output channels and store.
template<int S>
__device__ __forceinline__ void assign_cell(int local,
                                            const float4* __restrict__ bboxes4,
                                            const int*    __restrict__ labels,
                                            float*        __restrict__ out)
{
    const int b    = local / (S * S);
    const int cell = local % (S * S);
    const int ii = cell % S;   // x
    const int jj = cell / S;   // y

    const float stride     = 416.0f / (float)S;
    const float inv_stride = (float)S / 416.0f;   // exact (stride = 32/16/8)
    const float fii = (float)ii;
    const float fjj = (float)jj;
    const float cxc = (fii + 0.5f) * stride;
    const float cyc = (fjj + 0.5f) * stride;

    unsigned clsmask = 0u;
    float reg0 = 0.f, reg1 = 0.f, reg2 = 0.f, reg3 = 0.f, reg4 = 0.f;

    const float4* bb = bboxes4 + b * 32;
    const int*    lb = labels  + b * 32;

    #pragma unroll 4
    for (int n = 0; n < 32; ++n) {
        const float4 bx = __ldg(bb + n);
        const float cx = bx.x, cy = bx.y, bw = bx.z, bh = bx.w;

        const float pos0 = floorf(cx * inv_stride);
        const float pos1 = floorf(cy * inv_stride);
        const float bp0  = floorf(0.5f * bw * inv_stride);
        const float bp1  = floorf(0.5f * bh * inv_stride);

        const bool region = (fii >= pos0 - bp0) && (fii < pos0 + bp0) &&
                            (fjj >= pos1 - bp1) && (fjj < pos1 + bp1);

        if (region) clsmask |= (1u << __ldg(lb + n));

        const float hw = floorf(bw * 0.5f);
        const float hh = floorf(bh * 0.5f);
        const float l  = cxc - (cx - hw);
        const float r  = (cx + hw) - cxc;
        const float t  = cyc - (cy - hh);
        const float bo = (cy + hh) - cyc;

        const float mlr = fmaxf(l, r);
        const float mtb = fmaxf(t, bo);
        const float m   = fmaxf(mlr, mtb);

        bool band;
        if (S == 13)      band = (m > 256.0f);
        else if (S == 26) band = (m > 64.0f) && (m <= 256.0f);
        else              band = (m <= 64.0f);

        if (region && band) {
            const float regmax = fmaxf(fmaxf(fmaxf(reg0, reg1), fmaxf(reg2, reg3)), reg4);
            if (regmax == 0.0f || m < regmax) {
                const float cent = sqrtf(fminf(l, r) * fminf(t, bo) / (mlr * mtb));
                reg0 = fmaxf(l  * inv_stride, 0.0f);
                reg1 = fmaxf(t  * inv_stride, 0.0f);
                reg2 = fmaxf(r  * inv_stride, 0.0f);
                reg3 = fmaxf(bo * inv_stride, 0.0f);
                reg4 = fmaxf(cent, 0.0f);
            }
        }
    }

    float* o = out + (size_t)local * 25;   // [B, S(j), S(i), 25] is exactly local-major
    #pragma unroll
    for (int c = 0; c < 20; ++c)
        o[c] = ((clsmask >> c) & 1u) ? 1.0f : 0.0f;
    o[20] = reg0; o[21] = reg1; o[22] = reg2; o[23] = reg3; o[24] = reg4;
}

__global__ __launch_bounds__(THREADS)
void fused_kernel(const float4* __restrict__ img4,
                  float4*       __restrict__ out4,
                  int n4,
                  const float4* __restrict__ bboxes4,
                  const int*    __restrict__ labels,
                  float*        __restrict__ o13,
                  float*        __restrict__ o26,
                  float*        __restrict__ o52)
{
    // Phase 1: target assignment on the first ABLK blocks (warp-uniform scale:
    // C13 and C13+C26 are multiples of 32, so no intra-warp scale divergence).
    const int bid = blockIdx.x;
    if (bid < ABLK) {
        const int g = bid * THREADS + threadIdx.x;
        if (g < C13)              assign_cell<13>(g,             bboxes4, labels, o13);
        else if (g < C13 + C26)   assign_cell<26>(g - C13,       bboxes4, labels, o26);
        else if (g < TOT_CELLS)   assign_cell<52>(g - C13 - C26, bboxes4, labels, o52);
    }

    // Phase 2: all blocks copy the image, grid-stride over float4.
    const int stride = NB * THREADS;
    int i = bid * THREADS + threadIdx.x;
    // unrolled-by-2 main loop for a little more MLP
    for (; i + stride < n4; i += 2 * stride) {
        float4 a = img4[i];
        float4 b = img4[i + stride];
        out4[i]          = a;
        out4[i + stride] = b;
    }
    if (i < n4) out4[i] = img4[i];
}

extern "C" void kernel_launch(void* const* d_in, const int* in_sizes, int n_in,
                              void* d_out, int out_size)
{
    const float* image  = (const float*)d_in[0];
    const float* bboxes = (const float*)d_in[1];
    const int*   labels = (const int*)  d_in[2];
    float* out = (float*)d_out;

    const size_t n_img = (size_t)in_sizes[0];   // 33,226,752 (divisible by 4)
    const int n4 = (int)(n_img / 4);

    float* o13 = out + n_img;
    float* o26 = o13 + (size_t)BATCH * 13 * 13 * 25;
    float* o52 = o26 + (size_t)BATCH * 26 * 26 * 25;

    fused_kernel<<<NB, THREADS>>>((const float4*)image, (float4*)out, n4,
                                  (const float4*)bboxes, labels, o13, o26, o52);
}

// round 11
// speedup vs baseline: 1.5113x; 1.0764x over previous
#include <cuda_runtime.h>
#include <cstddef>

// ---- constants ----------------------------------------------------------
constexpr int BATCH = 64;
constexpr int C13 = BATCH * 13 * 13;            // 10816  (mult of 32)
constexpr int C26 = BATCH * 26 * 26;            // 43264
constexpr int C52 = BATCH * 52 * 52;            // 173056
constexpr int TOT_CELLS = C13 + C26 + C52;      // 227136
constexpr int THREADS = 256;
constexpr int ABLK = (TOT_CELLS + THREADS - 1) / THREADS;   // 888 (last partial: 64 cells)
constexpr int NB = 3256;                                     // total blocks

// One FCOS cell -> 25 floats into smem staging (stride-25, conflict-free).
template<int S>
__device__ __forceinline__ void assign_cell(int local,
                                            const float4* __restrict__ bboxes4,
                                            const int*    __restrict__ labels,
                                            float*        __restrict__ st)  // &stage[tid*25]
{
    const int b    = local / (S * S);
    const int cell = local % (S * S);
    const int ii = cell % S;   // x
    const int jj = cell / S;   // y

    const float stride     = 416.0f / (float)S;
    const float inv_stride = (float)S / 416.0f;   // exact (stride = 32/16/8)
    const float fii = (float)ii;
    const float fjj = (float)jj;
    const float cxc = (fii + 0.5f) * stride;
    const float cyc = (fjj + 0.5f) * stride;

    unsigned clsmask = 0u;
    float reg0 = 0.f, reg1 = 0.f, reg2 = 0.f, reg3 = 0.f, reg4 = 0.f;

    const float4* bb = bboxes4 + b * 32;
    const int*    lb = labels  + b * 32;

    #pragma unroll 4
    for (int n = 0; n < 32; ++n) {
        const float4 bx = __ldg(bb + n);
        const float cx = bx.x, cy = bx.y, bw = bx.z, bh = bx.w;

        const float pos0 = floorf(cx * inv_stride);
        const float pos1 = floorf(cy * inv_stride);
        const float bp0  = floorf(0.5f * bw * inv_stride);
        const float bp1  = floorf(0.5f * bh * inv_stride);

        const bool region = (fii >= pos0 - bp0) && (fii < pos0 + bp0) &&
                            (fjj >= pos1 - bp1) && (fjj < pos1 + bp1);

        if (region) clsmask |= (1u << __ldg(lb + n));

        const float hw = floorf(bw * 0.5f);
        const float hh = floorf(bh * 0.5f);
        const float l  = cxc - (cx - hw);
        const float r  = (cx + hw) - cxc;
        const float t  = cyc - (cy - hh);
        const float bo = (cy + hh) - cyc;

        const float mlr = fmaxf(l, r);
        const float mtb = fmaxf(t, bo);
        const float m   = fmaxf(mlr, mtb);

        bool band;
        if (S == 13)      band = (m > 256.0f);
        else if (S == 26) band = (m > 64.0f) && (m <= 256.0f);
        else              band = (m <= 64.0f);

        if (region && band) {
            const float regmax = fmaxf(fmaxf(fmaxf(reg0, reg1), fmaxf(reg2, reg3)), reg4);
            if (regmax == 0.0f || m < regmax) {
                const float cent = sqrtf(fminf(l, r) * fminf(t, bo) / (mlr * mtb));
                reg0 = fmaxf(l  * inv_stride, 0.0f);
                reg1 = fmaxf(t  * inv_stride, 0.0f);
                reg2 = fmaxf(r  * inv_stride, 0.0f);
                reg3 = fmaxf(bo * inv_stride, 0.0f);
                reg4 = fmaxf(cent, 0.0f);
            }
        }
    }

    #pragma unroll
    for (int c = 0; c < 20; ++c)
        st[c] = ((clsmask >> c) & 1u) ? 1.0f : 0.0f;
    st[20] = reg0; st[21] = reg1; st[22] = reg2; st[23] = reg3; st[24] = reg4;
}

__global__ __launch_bounds__(THREADS)
void fused_kernel(const float4* __restrict__ img4,
                  float4*       __restrict__ out4,
                  int n4,
                  const float4* __restrict__ bboxes4,
                  const int*    __restrict__ labels,
                  float*        __restrict__ out_t)   // contiguous target region (cell*25)
{
    __shared__ float stage[THREADS * 25];   // 25.6 KB

    const int bid = blockIdx.x;
    const int tid = threadIdx.x;

    // ---- Phase 1: FCOS assignment, smem-staged, coalesced float4 store ----
    if (bid < ABLK) {
        const int g = bid * THREADS + tid;
        if (g < C13)              assign_cell<13>(g,             bboxes4, labels, &stage[tid * 25]);
        else if (g < C13 + C26)   assign_cell<26>(g - C13,       bboxes4, labels, &stage[tid * 25]);
        else if (g < TOT_CELLS)   assign_cell<52>(g - C13 - C26, bboxes4, labels, &stage[tid * 25]);
        __syncthreads();

        const int ncells = min(THREADS, TOT_CELLS - bid * THREADS);
        const int nf4 = (ncells * 25) / 4;                     // 1600 or 400 (both exact)
        float4* dst = reinterpret_cast<float4*>(out_t + (size_t)bid * THREADS * 25);
        const float4* src = reinterpret_cast<const float4*>(stage);
        for (int k = tid; k < nf4; k += THREADS)
            dst[k] = src[k];
    }

    // ---- Phase 2: image copy, grid-stride, MLP-4 streaming ----
    const int stride = NB * THREADS;
    int i = bid * THREADS + tid;
    for (; i + 3 * stride < n4; i += 4 * stride) {
        float4 a = __ldcs(img4 + i);
        float4 b = __ldcs(img4 + i + stride);
        float4 c = __ldcs(img4 + i + 2 * stride);
        float4 d = __ldcs(img4 + i + 3 * stride);
        __stcs(out4 + i,              a);
        __stcs(out4 + i + stride,     b);
        __stcs(out4 + i + 2 * stride, c);
        __stcs(out4 + i + 3 * stride, d);
    }
    for (; i < n4; i += stride)
        __stcs(out4 + i, __ldcs(img4 + i));
}

extern "C" void kernel_launch(void* const* d_in, const int* in_sizes, int n_in,
                              void* d_out, int out_size)
{
    const float* image  = (const float*)d_in[0];
    const float* bboxes = (const float*)d_in[1];
    const int*   labels = (const int*)  d_in[2];
    float* out = (float*)d_out;

    const size_t n_img = (size_t)in_sizes[0];   // 33,226,752 (div by 4; *4B div by 16)
    const int n4 = (int)(n_img / 4);

    float* out_t = out + n_img;   // o13 | o26 | o52 are contiguous: flat cell*25 array

    fused_kernel<<<NB, THREADS>>>((const float4*)image, (float4*)out, n4,
                                  (const float4*)bboxes, labels, out_t);
}

// round 12
// speedup vs baseline: 1.6101x; 1.0654x over previous
#include <cuda_runtime.h>
#include <cstddef>

// ---- constants ----------------------------------------------------------
constexpr int BATCH = 64;
constexpr int C13 = BATCH * 13 * 13;            // 10816  (mult of 32)
constexpr int C26 = BATCH * 26 * 26;            // 43264
constexpr int C52 = BATCH * 52 * 52;            // 173056
constexpr int TOT_CELLS = C13 + C26 + C52;      // 227136
constexpr int THREADS = 256;
constexpr int ABLK = (TOT_CELLS + THREADS - 1) / THREADS;   // 888 assign-only blocks
constexpr int CBLK = 1480;                                   // copy-only blocks
constexpr int NB   = ABLK + CBLK;                            // 2368 = 2 waves @ 8 blk/SM

// One FCOS cell -> 25 floats into smem staging (stride-25, conflict-free).
template<int S>
__device__ __forceinline__ void assign_cell(int local,
                                            const float4* __restrict__ bboxes4,
                                            const int*    __restrict__ labels,
                                            float*        __restrict__ st)  // &stage[tid*25]
{
    const int b    = local / (S * S);
    const int cell = local % (S * S);
    const int ii = cell % S;   // x
    const int jj = cell / S;   // y

    const float stride     = 416.0f / (float)S;
    const float inv_stride = (float)S / 416.0f;   // exact (stride = 32/16/8)
    const float fii = (float)ii;
    const float fjj = (float)jj;
    const float cxc = (fii + 0.5f) * stride;
    const float cyc = (fjj + 0.5f) * stride;

    unsigned clsmask = 0u;
    float reg0 = 0.f, reg1 = 0.f, reg2 = 0.f, reg3 = 0.f, reg4 = 0.f;

    const float4* bb = bboxes4 + b * 32;
    const int*    lb = labels  + b * 32;

    #pragma unroll 4
    for (int n = 0; n < 32; ++n) {
        const float4 bx = __ldg(bb + n);
        const float cx = bx.x, cy = bx.y, bw = bx.z, bh = bx.w;

        const float pos0 = floorf(cx * inv_stride);
        const float pos1 = floorf(cy * inv_stride);
        const float bp0  = floorf(0.5f * bw * inv_stride);
        const float bp1  = floorf(0.5f * bh * inv_stride);

        const bool region = (fii >= pos0 - bp0) && (fii < pos0 + bp0) &&
                            (fjj >= pos1 - bp1) && (fjj < pos1 + bp1);

        if (region) clsmask |= (1u << __ldg(lb + n));

        const float hw = floorf(bw * 0.5f);
        const float hh = floorf(bh * 0.5f);
        const float l  = cxc - (cx - hw);
        const float r  = (cx + hw) - cxc;
        const float t  = cyc - (cy - hh);
        const float bo = (cy + hh) - cyc;

        const float mlr = fmaxf(l, r);
        const float mtb = fmaxf(t, bo);
        const float m   = fmaxf(mlr, mtb);

        bool band;
        if (S == 13)      band = (m > 256.0f);
        else if (S == 26) band = (m > 64.0f) && (m <= 256.0f);
        else              band = (m <= 64.0f);

        if (region && band) {
            const float regmax = fmaxf(fmaxf(fmaxf(reg0, reg1), fmaxf(reg2, reg3)), reg4);
            if (regmax == 0.0f || m < regmax) {
                const float cent = sqrtf(fminf(l, r) * fminf(t, bo) / (mlr * mtb));
                reg0 = fmaxf(l  * inv_stride, 0.0f);
                reg1 = fmaxf(t  * inv_stride, 0.0f);
                reg2 = fmaxf(r  * inv_stride, 0.0f);
                reg3 = fmaxf(bo * inv_stride, 0.0f);
                reg4 = fmaxf(cent, 0.0f);
            }
        }
    }

    #pragma unroll
    for (int c = 0; c < 20; ++c)
        st[c] = ((clsmask >> c) & 1u) ? 1.0f : 0.0f;
    st[20] = reg0; st[21] = reg1; st[22] = reg2; st[23] = reg3; st[24] = reg4;
}

__global__ __launch_bounds__(THREADS)
void fused_kernel(const float4* __restrict__ img4,
                  float4*       __restrict__ out4,
                  int n4,
                  const float4* __restrict__ bboxes4,
                  const int*    __restrict__ labels,
                  float*        __restrict__ out_t)   // contiguous target region (cell*25)
{
    const int bid = blockIdx.x;
    const int tid = threadIdx.x;

    if (bid < ABLK) {
        // ---- Assign-only blocks: FCOS targets, smem-staged, coalesced out ----
        __shared__ float stage[THREADS * 25];   // 25.6 KB

        const int g = bid * THREADS + tid;
        if (g < C13)              assign_cell<13>(g,             bboxes4, labels, &stage[tid * 25]);
        else if (g < C13 + C26)   assign_cell<26>(g - C13,       bboxes4, labels, &stage[tid * 25]);
        else if (g < TOT_CELLS)   assign_cell<52>(g - C13 - C26, bboxes4, labels, &stage[tid * 25]);
        __syncthreads();

        const int ncells = min(THREADS, TOT_CELLS - bid * THREADS);
        const int nf4 = (ncells * 25) / 4;                     // 1600 or 400 (both exact)
        float4* dst = reinterpret_cast<float4*>(out_t + (size_t)bid * THREADS * 25);
        const float4* src = reinterpret_cast<const float4*>(stage);
        for (int k = tid; k < nf4; k += THREADS)
            dst[k] = src[k];
    } else {
        // ---- Copy-only blocks: image passthrough, grid-stride, MLP-4 ----
        const int cb = bid - ABLK;                 // 0..CBLK-1
        const int stride = CBLK * THREADS;
        int i = cb * THREADS + tid;
        for (; i + 3 * stride < n4; i += 4 * stride) {
            float4 a = __ldcs(img4 + i);
            float4 b = __ldcs(img4 + i + stride);
            float4 c = __ldcs(img4 + i + 2 * stride);
            float4 d = __ldcs(img4 + i + 3 * stride);
            __stcs(out4 + i,              a);
            __stcs(out4 + i + stride,     b);
            __stcs(out4 + i + 2 * stride, c);
            __stcs(out4 + i + 3 * stride, d);
        }
        for (; i < n4; i += stride)
            __stcs(out4 + i, __ldcs(img4 + i));
    }
}

extern "C" void kernel_launch(void* const* d_in, const int* in_sizes, int n_in,
                              void* d_out, int out_size)
{
    const float* image  = (const float*)d_in[0];
    const float* bboxes = (const float*)d_in[1];
    const int*   labels = (const int*)  d_in[2];
    float* out = (float*)d_out;

    const size_t n_img = (size_t)in_sizes[0];   // 33,226,752 (div by 4; *4B div by 16)
    const int n4 = (int)(n_img / 4);

    float* out_t = out + n_img;   // o13 | o26 | o52 contiguous: flat cell*25 array

    fused_kernel<<<NB, THREADS>>>((const float4*)image, (float4*)out, n4,
                                  (const float4*)bboxes, labels, out_t);
}